// round 3
// baseline (speedup 1.0000x reference)
#include <cuda_runtime.h>
#include <math.h>

#define NN   30000
#define FIN  500
#define HID  16
#define NE   960000

// ---- scratch (static device allocations; no cudaMalloc allowed) ----
__device__ float g_h [NN * HID];   // pooled conv features
__device__ float g_p1[NN * HID];   // (h @ W1) * dinv
__device__ float g_q1[NN * HID];   // aggregated layer-1
__device__ float g_p2[NN * 4];     // (a @ W2) * dinv  (padded to 4)
__device__ float g_q2[NN * 4];     // aggregated layer-2
__device__ float g_deg [NN];
__device__ float g_dinv[NN];

// ============================================================================
// Fused conv1(1->16,k3) + relu + conv2(16->16,k3) + relu + max-pool(len 500)
// One warp per node. 8 warps / block.
// ============================================================================
__global__ void __launch_bounds__(256) conv_fused_kernel(
    const float* __restrict__ x,
    const float* __restrict__ w1,   // (16,1,3)
    const float* __restrict__ b1,
    const float* __restrict__ w2,   // (16,16,3)
    const float* __restrict__ b2)
{
    __shared__ float xs[8][504];
    __shared__ float w1s[3][16];          // [k][c]
    __shared__ float b1s[16];
    __shared__ float w2s[16 * 48];        // [co][k][ci] : co*48 + k*16 + ci
    __shared__ float b2s[16];

    const int tid = threadIdx.x;

    // cooperative weight staging (with permutation for float4 LDS)
    for (int i = tid; i < 16 * 48; i += 256) {
        int co = i / 48, r = i % 48, k = r / 16, ci = r % 16;
        w2s[i] = w2[co * 48 + ci * 3 + k];
    }
    if (tid < 48)       w1s[tid % 3][tid / 3] = w1[tid];   // w1s[k][c] = w1[c*3+k]
    else if (tid < 64)  b1s[tid - 48] = b1[tid - 48];
    else if (tid < 80)  b2s[tid - 64] = b2[tid - 64];

    const int warp = tid >> 5, lane = tid & 31;
    const int node = blockIdx.x * 8 + warp;   // 3750 * 8 == 30000 exactly

    // stage this node's x row (with +1 shift so xs[i+1] = x[i]; zero pads)
    const float* xr = x + (size_t)node * FIN;
    for (int i = lane; i < FIN; i += 32) xs[warp][i + 1] = xr[i];
    if (lane == 0) { xs[warp][0] = 0.f; xs[warp][501] = 0.f; xs[warp][502] = 0.f; xs[warp][503] = 0.f; }
    __syncthreads();

    float maxv[16];
#pragma unroll
    for (int c = 0; c < 16; c++) maxv[c] = -1e30f;

    for (int it = 0; it < 16; it++) {
        const int t = it * 32 + lane;
        const bool valid = (t < FIN);

        // conv1 columns at u = t-1, t, t+1 (zero column when outside [0,500))
        float h1[3][16];
#pragma unroll
        for (int j = 0; j < 3; j++) {
            const int u = t - 1 + j;
            const bool uok = valid && (u >= 0) && (u < FIN);
            const float xm = uok ? xs[warp][u]     : 0.f;   // x[u-1]
            const float xc = uok ? xs[warp][u + 1] : 0.f;   // x[u]
            const float xp = uok ? xs[warp][u + 2] : 0.f;   // x[u+1]
#pragma unroll
            for (int c = 0; c < 16; c++) {
                float a = b1s[c];
                a = fmaf(w1s[0][c], xm, a);
                a = fmaf(w1s[1][c], xc, a);
                a = fmaf(w1s[2][c], xp, a);
                h1[j][c] = uok ? fmaxf(a, 0.f) : 0.f;
            }
        }

        if (valid) {
#pragma unroll
            for (int co = 0; co < 16; co++) {
                float acc = b2s[co];
#pragma unroll
                for (int k = 0; k < 3; k++) {
                    const float4* wp = (const float4*)&w2s[co * 48 + k * 16];
#pragma unroll
                    for (int q = 0; q < 4; q++) {
                        const float4 w = wp[q];
                        acc = fmaf(w.x, h1[k][q * 4 + 0], acc);
                        acc = fmaf(w.y, h1[k][q * 4 + 1], acc);
                        acc = fmaf(w.z, h1[k][q * 4 + 2], acc);
                        acc = fmaf(w.w, h1[k][q * 4 + 3], acc);
                    }
                }
                maxv[co] = fmaxf(maxv[co], acc);
            }
        }
    }

    // warp max-reduce; relu commutes with max
#pragma unroll
    for (int c = 0; c < 16; c++) {
        float v = maxv[c];
#pragma unroll
        for (int off = 16; off > 0; off >>= 1)
            v = fmaxf(v, __shfl_xor_sync(0xffffffffu, v, off));
        maxv[c] = v;
    }
    if (lane == 0) {
#pragma unroll
        for (int c = 0; c < 16; c++) g_h[node * 16 + c] = fmaxf(maxv[c], 0.f);
    }
}

// ============================================================================
// Degree / dinv
// ============================================================================
__global__ void deg_init_kernel()
{
    int i = blockIdx.x * 256 + threadIdx.x;
    if (i < NN) g_deg[i] = 1.0f;            // self loop
}

__global__ void deg_count_kernel(const int* __restrict__ ei)
{
    int e = blockIdx.x * 256 + threadIdx.x;
    if (e < NE) atomicAdd(&g_deg[ei[NE + e]], 1.0f);   // dst
}

__global__ void dinv_kernel()
{
    int i = blockIdx.x * 256 + threadIdx.x;
    if (i < NN) g_dinv[i] = rsqrtf(g_deg[i]);
}

// ============================================================================
// GCN layer 1 pre: p1 = (h @ W1) * dinv ; q1 = p1 (self-loop term)
// ============================================================================
__global__ void __launch_bounds__(256) gcn1_pre_kernel(const float* __restrict__ W)
{
    __shared__ float Ws[256];
    Ws[threadIdx.x] = W[threadIdx.x];
    __syncthreads();

    int node = blockIdx.x * 256 + threadIdx.x;
    if (node >= NN) return;

    const float4* hr = (const float4*)(g_h + node * 16);
    float hv[16];
    float4 t0 = hr[0], t1 = hr[1], t2 = hr[2], t3 = hr[3];
    hv[0]=t0.x; hv[1]=t0.y; hv[2]=t0.z; hv[3]=t0.w;
    hv[4]=t1.x; hv[5]=t1.y; hv[6]=t1.z; hv[7]=t1.w;
    hv[8]=t2.x; hv[9]=t2.y; hv[10]=t2.z; hv[11]=t2.w;
    hv[12]=t3.x; hv[13]=t3.y; hv[14]=t3.z; hv[15]=t3.w;

    float acc[16];
#pragma unroll
    for (int c = 0; c < 16; c++) acc[c] = 0.f;
#pragma unroll
    for (int ci = 0; ci < 16; ci++) {
        const float hvi = hv[ci];
#pragma unroll
        for (int c4 = 0; c4 < 4; c4++) {
            const float4 w = *(const float4*)&Ws[ci * 16 + c4 * 4];
            acc[c4*4+0] = fmaf(hvi, w.x, acc[c4*4+0]);
            acc[c4*4+1] = fmaf(hvi, w.y, acc[c4*4+1]);
            acc[c4*4+2] = fmaf(hvi, w.z, acc[c4*4+2]);
            acc[c4*4+3] = fmaf(hvi, w.w, acc[c4*4+3]);
        }
    }
    const float di = g_dinv[node];
    float4* pp = (float4*)(g_p1 + node * 16);
    float4* qq = (float4*)(g_q1 + node * 16);
#pragma unroll
    for (int c4 = 0; c4 < 4; c4++) {
        float4 v;
        v.x = acc[c4*4+0]*di; v.y = acc[c4*4+1]*di;
        v.z = acc[c4*4+2]*di; v.w = acc[c4*4+3]*di;
        pp[c4] = v; qq[c4] = v;
    }
}

// ============================================================================
// Edge aggregation layer 1: q1[dst] += p1[src]  (4 threads per edge)
// ============================================================================
__global__ void edge_agg16_kernel(const int* __restrict__ ei)
{
    int tid = blockIdx.x * 256 + threadIdx.x;
    int e = tid >> 2;
    if (e >= NE) return;
    int j = tid & 3;
    int s = ei[e], d = ei[NE + e];
    float4 v = *(const float4*)(g_p1 + s * 16 + j * 4);
    float* qd = g_q1 + d * 16 + j * 4;
    atomicAdd(qd + 0, v.x);
    atomicAdd(qd + 1, v.y);
    atomicAdd(qd + 2, v.z);
    atomicAdd(qd + 3, v.w);
}

// ============================================================================
// GCN layer 2 pre: a = relu(dinv*q1 + b1) ; p2 = (a @ W2) * dinv ; q2 = p2
// ============================================================================
__global__ void __launch_bounds__(256) gcn2_pre_kernel(
    const float* __restrict__ b1g, const float* __restrict__ W2)
{
    __shared__ float W2s[48];
    __shared__ float b1s[16];
    if (threadIdx.x < 48) W2s[threadIdx.x] = W2[threadIdx.x];
    if (threadIdx.x < 16) b1s[threadIdx.x] = b1g[threadIdx.x];
    __syncthreads();

    int node = blockIdx.x * 256 + threadIdx.x;
    if (node >= NN) return;

    const float di = g_dinv[node];
    const float4* qr = (const float4*)(g_q1 + node * 16);
    float a[16];
#pragma unroll
    for (int c4 = 0; c4 < 4; c4++) {
        float4 v = qr[c4];
        a[c4*4+0] = fmaxf(fmaf(di, v.x, b1s[c4*4+0]), 0.f);
        a[c4*4+1] = fmaxf(fmaf(di, v.y, b1s[c4*4+1]), 0.f);
        a[c4*4+2] = fmaxf(fmaf(di, v.z, b1s[c4*4+2]), 0.f);
        a[c4*4+3] = fmaxf(fmaf(di, v.w, b1s[c4*4+3]), 0.f);
    }
    float o0 = 0.f, o1 = 0.f, o2 = 0.f;
#pragma unroll
    for (int ci = 0; ci < 16; ci++) {
        o0 = fmaf(a[ci], W2s[ci * 3 + 0], o0);
        o1 = fmaf(a[ci], W2s[ci * 3 + 1], o1);
        o2 = fmaf(a[ci], W2s[ci * 3 + 2], o2);
    }
    float4 r; r.x = o0 * di; r.y = o1 * di; r.z = o2 * di; r.w = 0.f;
    *(float4*)(g_p2 + node * 4) = r;
    *(float4*)(g_q2 + node * 4) = r;
}

// ============================================================================
// Edge aggregation layer 2: q2[dst] += p2[src]  (3 channels)
// ============================================================================
__global__ void edge_agg3_kernel(const int* __restrict__ ei)
{
    int e = blockIdx.x * 256 + threadIdx.x;
    if (e >= NE) return;
    int s = ei[e], d = ei[NE + e];
    float4 v = *(const float4*)(g_p2 + s * 4);
    float* qd = g_q2 + d * 4;
    atomicAdd(qd + 0, v.x);
    atomicAdd(qd + 1, v.y);
    atomicAdd(qd + 2, v.z);
}

// ============================================================================
// Finalize: v = dinv*q2 + b2 ; log_softmax over 3 classes
// ============================================================================
__global__ void finalize_kernel(const float* __restrict__ b2g, float* __restrict__ out)
{
    int node = blockIdx.x * 256 + threadIdx.x;
    if (node >= NN) return;
    const float di = g_dinv[node];
    float4 q = *(const float4*)(g_q2 + node * 4);
    float v0 = fmaf(di, q.x, b2g[0]);
    float v1 = fmaf(di, q.y, b2g[1]);
    float v2 = fmaf(di, q.z, b2g[2]);
    float m = fmaxf(v0, fmaxf(v1, v2));
    float s = expf(v0 - m) + expf(v1 - m) + expf(v2 - m);
    float l = m + logf(s);
    out[node * 3 + 0] = v0 - l;
    out[node * 3 + 1] = v1 - l;
    out[node * 3 + 2] = v2 - l;
}

// ============================================================================
extern "C" void kernel_launch(void* const* d_in, const int* in_sizes, int n_in,
                              void* d_out, int out_size)
{
    const float* x   = (const float*)d_in[0];
    const float* c1w = (const float*)d_in[1];
    const float* c1b = (const float*)d_in[2];
    const float* c2w = (const float*)d_in[3];
    const float* c2b = (const float*)d_in[4];
    const float* g1w = (const float*)d_in[5];
    const float* g1b = (const float*)d_in[6];
    const float* g2w = (const float*)d_in[7];
    const float* g2b = (const float*)d_in[8];
    const int*   ei  = (const int*)d_in[9];
    float* out = (float*)d_out;

    const int nblk_node = (NN + 255) / 256;   // 118
    const int nblk_edge = (NE + 255) / 256;   // 3750

    deg_init_kernel <<<nblk_node, 256>>>();
    deg_count_kernel<<<nblk_edge, 256>>>(ei);
    dinv_kernel     <<<nblk_node, 256>>>();

    conv_fused_kernel<<<NN / 8, 256>>>(x, c1w, c1b, c2w, c2b);

    gcn1_pre_kernel <<<nblk_node, 256>>>(g1w);
    edge_agg16_kernel<<<(4 * NE + 255) / 256, 256>>>(ei);

    gcn2_pre_kernel <<<nblk_node, 256>>>(g1b, g2w);
    edge_agg3_kernel<<<nblk_edge, 256>>>(ei);

    finalize_kernel <<<nblk_node, 256>>>(g2b, out);
}